// round 16
// baseline (speedup 1.0000x reference)
#include <cuda_runtime.h>
#include <cuda_bf16.h>
#include <cstdint>

// ---------------- problem constants ----------------
#define BB   32
#define HH   56
#define CC   192
#define LL   (HH*HH)
#define NHD  6
#define HD   32
#define WSZ  7
#define SSH  3
#define NWIN 49
#define BW   2048
#define MROWS (BW*NWIN)        // 100352
#define HID  768
#define QSCALE 0.17677669529663687f

// ---------------- scratch ----------------
__device__ __nv_bfloat16 g_xw [(size_t)MROWS*CC];
__device__ __nv_bfloat16 g_qkv[(size_t)MROWS*3*CC];
__device__ __nv_bfloat16 g_o  [(size_t)MROWS*CC];
__device__ __nv_bfloat16 g_h1 [(size_t)MROWS*HID];
__device__ __nv_bfloat16 g_wq [(size_t)CC*3*CC];
__device__ __nv_bfloat16 g_wp [(size_t)CC*CC];
__device__ __nv_bfloat16 g_w1 [(size_t)CC*HID];
__device__ __nv_bfloat16 g_w2 [(size_t)HID*CC];
__device__ float         g_bm [(size_t)64*NHD*64*64];

__device__ __forceinline__ int remap_row(int m) {
    int w = m / NWIN, n = m - w * NWIN;
    int b = w >> 6, widx = w & 63;
    int wi = widx >> 3, wj = widx & 7;
    int ti = n / WSZ, tj = n - ti * WSZ;
    int i0 = wi * WSZ + ti + SSH; if (i0 >= HH) i0 -= HH;
    int j0 = wj * WSZ + tj + SSH; if (j0 >= HH) j0 -= HH;
    return b * LL + i0 * HH + j0;
}

// ---------------- all weights f32 -> bf16 in one kernel ----------------
#define CVT_N0 (CC*3*CC)
#define CVT_N1 (CVT_N0 + CC*CC)
#define CVT_N2 (CVT_N1 + CC*HID)
#define CVT_N3 (CVT_N2 + HID*CC)
__global__ void cvt_all(const float* __restrict__ s0, __nv_bfloat16* __restrict__ d0,
                        const float* __restrict__ s1, __nv_bfloat16* __restrict__ d1,
                        const float* __restrict__ s2, __nv_bfloat16* __restrict__ d2,
                        const float* __restrict__ s3, __nv_bfloat16* __restrict__ d3) {
    int i = blockIdx.x * 256 + threadIdx.x;
    if (i < CVT_N0)      d0[i]          = __float2bfloat16(s0[i]);
    else if (i < CVT_N1) d1[i - CVT_N0] = __float2bfloat16(s1[i - CVT_N0]);
    else if (i < CVT_N2) d2[i - CVT_N1] = __float2bfloat16(s2[i - CVT_N1]);
    else if (i < CVT_N3) d3[i - CVT_N2] = __float2bfloat16(s3[i - CVT_N2]);
}

// ---------------- precompute combined bias+mask tables -------------------
__global__ void bm_kernel(const float* __restrict__ rel_table,
                          const int* __restrict__ rel_index,
                          const float* __restrict__ mask,
                          float* __restrict__ bm) {
    int widx = blockIdx.x / NHD;
    int h    = blockIdx.x % NHD;
    float* dst = bm + (size_t)blockIdx.x * 4096;
    for (int e = threadIdx.x; e < 4096; e += 256) {
        int i = e >> 6, j = e & 63;
        float v = -1e30f;
        if (i < NWIN && j < NWIN)
            v = rel_table[rel_index[i * NWIN + j] * NHD + h]
              + mask[(size_t)widx * (NWIN * NWIN) + i * NWIN + j];
        dst[e] = v;
    }
}

// ---------------- LayerNorm (LN1 only): 8 rows/block, warp-per-row -------
__global__ __launch_bounds__(256) void ln1_kernel(
    const float* __restrict__ x, const float* __restrict__ g,
    const float* __restrict__ b, __nv_bfloat16* __restrict__ y) {
    int warp = threadIdx.x >> 5, lane = threadIdx.x & 31;
    int m = blockIdx.x * 8 + warp;
    int r = remap_row(m);
    const float* xr = x + (size_t)r * CC;
    float v[6];
    float s = 0.f, s2 = 0.f;
    #pragma unroll
    for (int k = 0; k < 6; k++) {
        v[k] = xr[lane + 32 * k];
        s += v[k]; s2 += v[k] * v[k];
    }
    #pragma unroll
    for (int off = 16; off; off >>= 1) {
        s  += __shfl_xor_sync(~0u, s,  off);
        s2 += __shfl_xor_sync(~0u, s2, off);
    }
    float mean = s * (1.f / CC);
    float var  = s2 * (1.f / CC) - mean * mean;
    float inv  = rsqrtf(var + 1e-5f);
    __nv_bfloat16* yr = y + (size_t)m * CC;
    #pragma unroll
    for (int k = 0; k < 6; k++) {
        int c = lane + 32 * k;
        yr[c] = __float2bfloat16((v[k] - mean) * inv * g[c] + b[c]);
    }
}

// ---------------- shared mma/ldsm helpers ----------------
__device__ __forceinline__ void ldsm_x4(uint32_t& r0, uint32_t& r1, uint32_t& r2,
                                        uint32_t& r3, uint32_t a) {
    asm volatile("ldmatrix.sync.aligned.m8n8.x4.shared.b16 {%0,%1,%2,%3}, [%4];"
                 : "=r"(r0), "=r"(r1), "=r"(r2), "=r"(r3) : "r"(a));
}
__device__ __forceinline__ void ldsm_x4t(uint32_t& r0, uint32_t& r1, uint32_t& r2,
                                         uint32_t& r3, uint32_t a) {
    asm volatile("ldmatrix.sync.aligned.m8n8.x4.trans.shared.b16 {%0,%1,%2,%3}, [%4];"
                 : "=r"(r0), "=r"(r1), "=r"(r2), "=r"(r3) : "r"(a));
}
__device__ __forceinline__ void mma_bf16(float* d, uint32_t a0, uint32_t a1,
                                         uint32_t a2, uint32_t a3,
                                         uint32_t b0, uint32_t b1) {
    asm volatile(
        "mma.sync.aligned.m16n8k16.row.col.f32.bf16.bf16.f32 "
        "{%0,%1,%2,%3}, {%4,%5,%6,%7}, {%8,%9}, {%0,%1,%2,%3};"
        : "+f"(d[0]), "+f"(d[1]), "+f"(d[2]), "+f"(d[3])
        : "r"(a0), "r"(a1), "r"(a2), "r"(a3), "r"(b0), "r"(b1));
}
__device__ __forceinline__ void cp16(uint32_t saddr, const void* g) {
    asm volatile("cp.async.cg.shared.global [%0], [%1], 16;" :: "r"(saddr), "l"(g));
}
#define CP_COMMIT() asm volatile("cp.async.commit_group;")
#define CP_WAIT1()  asm volatile("cp.async.wait_group 1;")

// ---------------- bf16 GEMM: 128x64 tile, 3 stages, 4 CTAs/SM ------------
#define GBM 128
#define GBN 64
#define AST 40
#define BST 72
#define STG_ELTS (GBM*AST + 32*BST)
#define NSTG 3
#define GEMM_SMEM (NSTG * STG_ELTS * 2)   // 44544 B

template<int EPI, int KK, typename TOut>
__global__ __launch_bounds__(256, 4) void gemm_tc(
    const __nv_bfloat16* __restrict__ A, const __nv_bfloat16* __restrict__ B,
    const float* __restrict__ bias, TOut* __restrict__ C,
    int M, int N, const float* __restrict__ resid)
{
    extern __shared__ __align__(16) __nv_bfloat16 sm[];
    uint32_t sbase = (uint32_t)__cvta_generic_to_shared(sm);

    int bm = blockIdx.y * GBM, bn = blockIdx.x * GBN;
    int tid = threadIdx.x, lane = tid & 31;
    int lp = lane >> 2, lq = lane & 3;
    int warp = tid >> 5, wm = warp & 3, wn = warp >> 2;

    int a_r0 = tid >> 2;
    int a_c  = (tid & 3) * 8;
    int b_r  = tid >> 3;
    int b_c  = (tid & 7) * 8;
    int lrow = (lane & 7) + ((lane >> 3) & 1) * 8;
    int lcol = (lane >> 4) * 8;

    constexpr int nk = KK >> 5;
    constexpr int UNR = 6;
    float acc[2][4][4] = {};

    auto issue = [&](int it) {
        int s = it % NSTG;
        uint32_t sa = sbase + (uint32_t)(s * STG_ELTS) * 2;
        int k0 = it << 5;
        cp16(sa + (uint32_t)(a_r0 * AST + a_c) * 2,
             A + (size_t)(bm + a_r0) * KK + k0 + a_c);
        cp16(sa + (uint32_t)((a_r0 + 64) * AST + a_c) * 2,
             A + (size_t)(bm + a_r0 + 64) * KK + k0 + a_c);
        cp16(sa + (uint32_t)(GBM * AST + b_r * BST + b_c) * 2,
             B + (size_t)(k0 + b_r) * N + bn + b_c);
    };

    uint32_t af[2][2][4];
    uint32_t bf[2][2][4];

    auto ldfrags = [&](uint32_t sa, uint32_t sb, int ks, int buf) {
        #pragma unroll
        for (int mt = 0; mt < 2; mt++)
            ldsm_x4(af[buf][mt][0], af[buf][mt][1], af[buf][mt][2], af[buf][mt][3],
                    sa + (uint32_t)((wm * 32 + mt * 16 + lrow) * AST + ks * 16 + lcol) * 2);
        #pragma unroll
        for (int g = 0; g < 2; g++)
            ldsm_x4t(bf[buf][g][0], bf[buf][g][1], bf[buf][g][2], bf[buf][g][3],
                     sb + (uint32_t)((ks * 16 + lrow) * BST + wn * 32 + g * 16 + lcol) * 2);
    };
    auto mmas = [&](int buf) {
        #pragma unroll
        for (int mt = 0; mt < 2; mt++)
            #pragma unroll
            for (int nt = 0; nt < 4; nt++) {
                int g = nt >> 1, h = nt & 1;
                mma_bf16(acc[mt][nt],
                         af[buf][mt][0], af[buf][mt][1], af[buf][mt][2], af[buf][mt][3],
                         bf[buf][g][h * 2], bf[buf][g][h * 2 + 1]);
            }
    };

    issue(0); CP_COMMIT();
    issue(1); CP_COMMIT();
    #pragma unroll 1
    for (int it0 = 0; it0 < nk; it0 += UNR) {
        #pragma unroll
        for (int u = 0; u < UNR; u++) {
            int it = it0 + u;
            CP_WAIT1();
            __syncthreads();
            if (it + 2 < nk) issue(it + 2);
            CP_COMMIT();
            int s = it % NSTG;
            uint32_t sa = sbase + (uint32_t)(s * STG_ELTS) * 2;
            uint32_t sb = sa + GBM * AST * 2;
            ldfrags(sa, sb, 0, 0);
            ldfrags(sa, sb, 1, 1);
            mmas(0);
            mmas(1);
        }
    }

    int m0 = wm * 32, n0 = wn * 32;
    #pragma unroll
    for (int mt = 0; mt < 2; mt++) {
        #pragma unroll
        for (int half = 0; half < 2; half++) {
            int m = bm + m0 + mt * 16 + lp + half * 8;
            int row = m;
            #pragma unroll
            for (int nt = 0; nt < 4; nt++) {
                int n = bn + n0 + nt * 8 + 2 * lq;
                float v0 = acc[mt][nt][half * 2 + 0] + bias[n];
                float v1 = acc[mt][nt][half * 2 + 1] + bias[n + 1];
                if constexpr (EPI == 0) {
                    if (n < CC) { v0 *= QSCALE; v1 *= QSCALE; }
                    *(__nv_bfloat162*)&((__nv_bfloat16*)C)[(size_t)row * N + n] =
                        __floats2bfloat162_rn(v0, v1);
                } else if constexpr (EPI == 2) {
                    v0 = 0.5f * v0 * (1.f + erff(v0 * 0.70710678118654752f));
                    v1 = 0.5f * v1 * (1.f + erff(v1 * 0.70710678118654752f));
                    *(__nv_bfloat162*)&((__nv_bfloat16*)C)[(size_t)row * N + n] =
                        __floats2bfloat162_rn(v0, v1);
                } else {
                    const float2 cv = *(const float2*)&((float*)C)[(size_t)row * N + n];
                    *(float2*)&((float*)C)[(size_t)row * N + n] =
                        make_float2(v0 + cv.x, v1 + cv.y);
                }
            }
        }
    }
}

// ---------------- proj GEMM fused with residual + LN2 --------------------
// block 128x192 (full rows), 512 threads, 16 warps (4M x 4N), warp 32x48.
#define PAST 40
#define PBST 200
#define PSTG_ELTS (128*PAST + 32*PBST)   // 5120+6400 = 11520
#define PNSTG 3
#define PRED_OFF (PNSTG*PSTG_ELTS)       // bf16 elts before red buffer
#define PROJ_SMEM (PNSTG*PSTG_ELTS*2 + 2*4*128*4)   // 69120 + 4096 = 73216 B

__global__ __launch_bounds__(512) void proj_ln_tc(
    const __nv_bfloat16* __restrict__ A, const __nv_bfloat16* __restrict__ B,
    const float* __restrict__ bias, const float* __restrict__ x,
    float* __restrict__ out, const float* __restrict__ g2,
    const float* __restrict__ b2, __nv_bfloat16* __restrict__ xw)
{
    extern __shared__ __align__(16) __nv_bfloat16 sm[];
    uint32_t sbase = (uint32_t)__cvta_generic_to_shared(sm);
    float* redS = (float*)(sm + PRED_OFF);         // [4 wn][128 rows]
    float* redQ = redS + 4 * 128;

    int bm = blockIdx.x * 128;
    int tid = threadIdx.x, lane = tid & 31;
    int lp = lane >> 2, lq = lane & 3;
    int warp = tid >> 5, wm = warp & 3, wn = warp >> 2;
    int lrow = (lane & 7) + ((lane >> 3) & 1) * 8;
    int lcol = (lane >> 4) * 8;

    int a_r = tid >> 2;
    int a_c = (tid & 3) * 8;

    float acc[2][6][4] = {};

    auto issue = [&](int it) {
        int s = it % PNSTG;
        uint32_t sa = sbase + (uint32_t)(s * PSTG_ELTS) * 2;
        int k0 = it << 5;
        cp16(sa + (uint32_t)(a_r * PAST + a_c) * 2,
             A + (size_t)(bm + a_r) * CC + k0 + a_c);
        // B: 768 chunks (32 rows x 24 chunks)
        uint32_t sb = sa + 128 * PAST * 2;
        int c0 = tid;
        {
            int r = c0 / 24, c = (c0 - r * 24) * 8;
            cp16(sb + (uint32_t)(r * PBST + c) * 2, B + (size_t)(k0 + r) * CC + c);
        }
        if (tid < 256) {
            int c1 = tid + 512;
            int r = c1 / 24, c = (c1 - r * 24) * 8;
            cp16(sb + (uint32_t)(r * PBST + c) * 2, B + (size_t)(k0 + r) * CC + c);
        }
    };

    issue(0); CP_COMMIT();
    issue(1); CP_COMMIT();
    #pragma unroll
    for (int it = 0; it < 6; it++) {
        CP_WAIT1();
        __syncthreads();
        if (it + 2 < 6) issue(it + 2);
        CP_COMMIT();
        int s = it % PNSTG;
        uint32_t sa = sbase + (uint32_t)(s * PSTG_ELTS) * 2;
        uint32_t sb = sa + 128 * PAST * 2;
        #pragma unroll
        for (int ks = 0; ks < 2; ks++) {
            uint32_t a0, a1, a2, a3;
            ldsm_x4(a0, a1, a2, a3,
                    sa + (uint32_t)((wm * 32 + lrow) * PAST + ks * 16 + lcol) * 2);
            uint32_t a4, a5, a6, a7;
            ldsm_x4(a4, a5, a6, a7,
                    sa + (uint32_t)((wm * 32 + 16 + lrow) * PAST + ks * 16 + lcol) * 2);
            uint32_t bfr[3][4];
            #pragma unroll
            for (int g = 0; g < 3; g++)
                ldsm_x4t(bfr[g][0], bfr[g][1], bfr[g][2], bfr[g][3],
                         sb + (uint32_t)((ks * 16 + lrow) * PBST + wn * 48 + g * 16 + lcol) * 2);
            #pragma unroll
            for (int nt = 0; nt < 6; nt++) {
                int g = nt >> 1, h = nt & 1;
                mma_bf16(acc[0][nt], a0, a1, a2, a3, bfr[g][h * 2], bfr[g][h * 2 + 1]);
                mma_bf16(acc[1][nt], a4, a5, a6, a7, bfr[g][h * 2], bfr[g][h * 2 + 1]);
            }
        }
    }
    __syncthreads();   // stages done; smem reusable for reduction

    // epilogue: v = acc + bias + resid; row stats; out + LN -> xw
    int rowg[2][2];    // global (token) rows
    #pragma unroll
    for (int mt = 0; mt < 2; mt++)
        #pragma unroll
        for (int half = 0; half < 2; half++)
            rowg[mt][half] = remap_row(bm + wm * 32 + mt * 16 + lp + half * 8);

    float s_[2][2] = {}, q_[2][2] = {};
    #pragma unroll
    for (int mt = 0; mt < 2; mt++) {
        #pragma unroll
        for (int half = 0; half < 2; half++) {
            int row = rowg[mt][half];
            #pragma unroll
            for (int nt = 0; nt < 6; nt++) {
                int n = wn * 48 + nt * 8 + 2 * lq;
                float2 rv = *(const float2*)&x[(size_t)row * CC + n];
                float v0 = acc[mt][nt][half * 2 + 0] + bias[n]     + rv.x;
                float v1 = acc[mt][nt][half * 2 + 1] + bias[n + 1] + rv.y;
                acc[mt][nt][half * 2 + 0] = v0;
                acc[mt][nt][half * 2 + 1] = v1;
                s_[mt][half] += v0 + v1;
                q_[mt][half] += v0 * v0 + v1 * v1;
            }
        }
    }
    #pragma unroll
    for (int mt = 0; mt < 2; mt++)
        #pragma unroll
        for (int half = 0; half < 2; half++) {
            s_[mt][half] += __shfl_xor_sync(~0u, s_[mt][half], 1);
            s_[mt][half] += __shfl_xor_sync(~0u, s_[mt][half], 2);
            q_[mt][half] += __shfl_xor_sync(~0u, q_[mt][half], 1);
            q_[mt][half] += __shfl_xor_sync(~0u, q_[mt][half], 2);
        }
    if (lq == 0) {
        #pragma unroll
        for (int mt = 0; mt < 2; mt++)
            #pragma unroll
            for (int half = 0; half < 2; half++) {
                int lr = wm * 32 + mt * 16 + lp + half * 8;
                redS[wn * 128 + lr] = s_[mt][half];
                redQ[wn * 128 + lr] = q_[mt][half];
            }
    }
    __syncthreads();

    #pragma unroll
    for (int mt = 0; mt < 2; mt++) {
        #pragma unroll
        for (int half = 0; half < 2; half++) {
            int lr  = wm * 32 + mt * 16 + lp + half * 8;
            int row = rowg[mt][half];
            float ts = redS[lr] + redS[128 + lr] + redS[256 + lr] + redS[384 + lr];
            float tq = redQ[lr] + redQ[128 + lr] + redQ[256 + lr] + redQ[384 + lr];
            float mean = ts * (1.f / CC);
            float var  = tq * (1.f / CC) - mean * mean;
            float inv  = rsqrtf(var + 1e-5f);
            #pragma unroll
            for (int nt = 0; nt < 6; nt++) {
                int n = wn * 48 + nt * 8 + 2 * lq;
                float v0 = acc[mt][nt][half * 2 + 0];
                float v1 = acc[mt][nt][half * 2 + 1];
                *(float2*)&out[(size_t)row * CC + n] = make_float2(v0, v1);
                float y0 = (v0 - mean) * inv * g2[n]     + b2[n];
                float y1 = (v1 - mean) * inv * g2[n + 1] + b2[n + 1];
                *(__nv_bfloat162*)&xw[(size_t)row * CC + n] =
                    __floats2bfloat162_rn(y0, y1);
            }
        }
    }
}

// ---------------- tensor-core windowed attention ----------------
#define NP  64
#define QST 40
#define PST 72

__global__ __launch_bounds__(128) void attn_tc(
    const __nv_bfloat16* __restrict__ qkv, const float* __restrict__ bm_tab,
    __nv_bfloat16* __restrict__ o)
{
    __shared__ __align__(16) __nv_bfloat16 sQ[NP * QST];
    __shared__ __align__(16) __nv_bfloat16 sK[NP * QST];
    __shared__ __align__(16) __nv_bfloat16 sV[NP * QST];
    __shared__ __align__(16) __nv_bfloat16 sP[NP * PST];

    int w = blockIdx.x, h = blockIdx.y, widx = w & 63;
    int tid = threadIdx.x, lane = tid & 31, warp = tid >> 5;
    int lp = lane >> 2, lq = lane & 3;
    int lrow = (lane & 7) + ((lane >> 3) & 1) * 8;
    int lcol = (lane >> 4) * 8;

    const float* bm = bm_tab + (size_t)(widx * NHD + h) * 4096;

    const __nv_bfloat16* qbase = qkv + (size_t)(w * NWIN) * (3 * CC) + h * HD;
    for (int idx = tid; idx < 3 * 64 * 4; idx += 128) {
        int t   = idx >> 8;
        int row = (idx >> 2) & 63;
        int ch  = idx & 3;
        uint4 val = make_uint4(0, 0, 0, 0);
        if (row < NWIN)
            val = *(const uint4*)(qbase + (size_t)row * (3 * CC) + t * CC + ch * 8);
        __nv_bfloat16* dst = (t == 0) ? sQ : (t == 1) ? sK : sV;
        *(uint4*)(dst + row * QST + ch * 8) = val;
    }
    __syncthreads();

    uint32_t qb = (uint32_t)__cvta_generic_to_shared(sQ);
    uint32_t kb = (uint32_t)__cvta_generic_to_shared(sK);
    uint32_t vb = (uint32_t)__cvta_generic_to_shared(sV);
    uint32_t pb = (uint32_t)__cvta_generic_to_shared(sP);

    float S[8][4] = {};
    #pragma unroll
    for (int ks = 0; ks < 2; ks++) {
        uint32_t a0, a1, a2, a3;
        ldsm_x4(a0, a1, a2, a3,
                qb + (uint32_t)((warp * 16 + lrow) * QST + ks * 16 + lcol) * 2);
        #pragma unroll
        for (int g = 0; g < 4; g++) {
            uint32_t r0, r1, r2, r3;
            ldsm_x4(r0, r1, r2, r3,
                    kb + (uint32_t)((g * 16 + lrow) * QST + ks * 16 + lcol) * 2);
            mma_bf16(S[g * 2],     a0, a1, a2, a3, r0, r2);
            mma_bf16(S[g * 2 + 1], a0, a1, a2, a3, r1, r3);
        }
    }

    int i0 = warp * 16 + lp;
    float mx0 = -1e30f, mx1 = -1e30f;
    #pragma unroll
    for (int nt = 0; nt < 8; nt++) {
        int c = nt * 8 + 2 * lq;
        float2 b0 = *(const float2*)&bm[i0 * 64 + c];
        float2 b1 = *(const float2*)&bm[(i0 + 8) * 64 + c];
        S[nt][0] += b0.x; S[nt][1] += b0.y;
        S[nt][2] += b1.x; S[nt][3] += b1.y;
        mx0 = fmaxf(mx0, fmaxf(S[nt][0], S[nt][1]));
        mx1 = fmaxf(mx1, fmaxf(S[nt][2], S[nt][3]));
    }
    mx0 = fmaxf(mx0, __shfl_xor_sync(~0u, mx0, 1));
    mx0 = fmaxf(mx0, __shfl_xor_sync(~0u, mx0, 2));
    mx1 = fmaxf(mx1, __shfl_xor_sync(~0u, mx1, 1));
    mx1 = fmaxf(mx1, __shfl_xor_sync(~0u, mx1, 2));
    float sm0 = 0.f, sm1 = 0.f;
    #pragma unroll
    for (int nt = 0; nt < 8; nt++) {
        S[nt][0] = __expf(S[nt][0] - mx0);
        S[nt][1] = __expf(S[nt][1] - mx0);
        S[nt][2] = __expf(S[nt][2] - mx1);
        S[nt][3] = __expf(S[nt][3] - mx1);
        sm0 += S[nt][0] + S[nt][1];
        sm1 += S[nt][2] + S[nt][3];
    }
    sm0 += __shfl_xor_sync(~0u, sm0, 1);
    sm0 += __shfl_xor_sync(~0u, sm0, 2);
    sm1 += __shfl_xor_sync(~0u, sm1, 1);
    sm1 += __shfl_xor_sync(~0u, sm1, 2);
    float inv0 = 1.f / sm0, inv1 = 1.f / sm1;
    #pragma unroll
    for (int nt = 0; nt < 8; nt++) {
        int c = nt * 8 + 2 * lq;
        *(__nv_bfloat162*)(sP + i0 * PST + c) =
            __floats2bfloat162_rn(S[nt][0] * inv0, S[nt][1] * inv0);
        *(__nv_bfloat162*)(sP + (i0 + 8) * PST + c) =
            __floats2bfloat162_rn(S[nt][2] * inv1, S[nt][3] * inv1);
    }
    __syncwarp();

    float O[4][4] = {};
    #pragma unroll
    for (int kst = 0; kst < 4; kst++) {
        uint32_t a0, a1, a2, a3;
        ldsm_x4(a0, a1, a2, a3,
                pb + (uint32_t)((warp * 16 + lrow) * PST + kst * 16 + lcol) * 2);
        #pragma unroll
        for (int g = 0; g < 2; g++) {
            uint32_t r0, r1, r2, r3;
            ldsm_x4t(r0, r1, r2, r3,
                     vb + (uint32_t)((kst * 16 + lrow) * QST + g * 16 + lcol) * 2);
            mma_bf16(O[g * 2],     a0, a1, a2, a3, r0, r1);
            mma_bf16(O[g * 2 + 1], a0, a1, a2, a3, r2, r3);
        }
    }

    __nv_bfloat16* obase = o + (size_t)(w * NWIN) * CC + h * HD;
    #pragma unroll
    for (int half = 0; half < 2; half++) {
        int i = i0 + half * 8;
        if (i < NWIN) {
            #pragma unroll
            for (int nt = 0; nt < 4; nt++) {
                int d = nt * 8 + 2 * lq;
                *(__nv_bfloat162*)(obase + (size_t)i * CC + d) =
                    __floats2bfloat162_rn(O[nt][half * 2], O[nt][half * 2 + 1]);
            }
        }
    }
}

// ---------------- launch ----------------
extern "C" void kernel_launch(void* const* d_in, const int* in_sizes, int n_in,
                              void* d_out, int out_size) {
    const float* x        = (const float*)d_in[0];
    const float* norm1_g  = (const float*)d_in[1];
    const float* norm1_b  = (const float*)d_in[2];
    const float* qkv_w    = (const float*)d_in[3];
    const float* qkv_b    = (const float*)d_in[4];
    const float* proj_w   = (const float*)d_in[5];
    const float* proj_b   = (const float*)d_in[6];
    const float* norm2_g  = (const float*)d_in[7];
    const float* norm2_b  = (const float*)d_in[8];
    const float* fc1_w    = (const float*)d_in[9];
    const float* fc1_b    = (const float*)d_in[10];
    const float* fc2_w    = (const float*)d_in[11];
    const float* fc2_b    = (const float*)d_in[12];
    const float* rel_table= (const float*)d_in[13];
    const int*   rel_index= (const int*)  d_in[14];
    const float* mask     = (const float*)d_in[15];
    float* out = (float*)d_out;

    __nv_bfloat16 *xw, *qkv, *o, *h1, *wq, *wp, *w1, *w2;
    float* bm;
    cudaGetSymbolAddress((void**)&xw,  g_xw);
    cudaGetSymbolAddress((void**)&qkv, g_qkv);
    cudaGetSymbolAddress((void**)&o,   g_o);
    cudaGetSymbolAddress((void**)&h1,  g_h1);
    cudaGetSymbolAddress((void**)&wq,  g_wq);
    cudaGetSymbolAddress((void**)&wp,  g_wp);
    cudaGetSymbolAddress((void**)&w1,  g_w1);
    cudaGetSymbolAddress((void**)&w2,  g_w2);
    cudaGetSymbolAddress((void**)&bm,  g_bm);

    cudaFuncSetAttribute((const void*)gemm_tc<0, CC, __nv_bfloat16>,
                         cudaFuncAttributeMaxDynamicSharedMemorySize, GEMM_SMEM);
    cudaFuncSetAttribute((const void*)gemm_tc<2, CC, __nv_bfloat16>,
                         cudaFuncAttributeMaxDynamicSharedMemorySize, GEMM_SMEM);
    cudaFuncSetAttribute((const void*)gemm_tc<3, HID, float>,
                         cudaFuncAttributeMaxDynamicSharedMemorySize, GEMM_SMEM);
    cudaFuncSetAttribute((const void*)proj_ln_tc,
                         cudaFuncAttributeMaxDynamicSharedMemorySize, PROJ_SMEM);

    cvt_all<<<(CVT_N3 + 255) / 256, 256>>>(qkv_w, wq, proj_w, wp, fc1_w, w1, fc2_w, w2);
    bm_kernel<<<64 * NHD, 256>>>(rel_table, rel_index, mask, bm);

    ln1_kernel<<<MROWS / 8, 256>>>(x, norm1_g, norm1_b, xw);
    gemm_tc<0, CC, __nv_bfloat16><<<dim3((3*CC)/GBN, MROWS/GBM), 256, GEMM_SMEM>>>(
        xw, wq, qkv_b, qkv, MROWS, 3*CC, nullptr);
    attn_tc<<<dim3(BW, NHD), 128>>>(qkv, bm, o);
    proj_ln_tc<<<MROWS/128, 512, PROJ_SMEM>>>(o, wp, proj_b, x, out,
                                              norm2_g, norm2_b, xw);
    gemm_tc<2, CC, __nv_bfloat16><<<dim3(HID/GBN, MROWS/GBM), 256, GEMM_SMEM>>>(
        xw, w1, fc1_b, h1, MROWS, HID, nullptr);
    gemm_tc<3, HID, float><<<dim3(CC/GBN, MROWS/GBM), 256, GEMM_SMEM>>>(
        h1, w2, fc2_b, out, MROWS, CC, nullptr);
}

// round 17
// speedup vs baseline: 1.0182x; 1.0182x over previous
#include <cuda_runtime.h>
#include <cuda_bf16.h>
#include <cstdint>

// ---------------- problem constants ----------------
#define BB   32
#define HH   56
#define CC   192
#define LL   (HH*HH)
#define NHD  6
#define HD   32
#define WSZ  7
#define SSH  3
#define NWIN 49
#define BW   2048
#define MROWS (BW*NWIN)        // 100352
#define HID  768
#define QSCALE 0.17677669529663687f

// ---------------- scratch ----------------
__device__ __nv_bfloat16 g_xw [(size_t)MROWS*CC];
__device__ __nv_bfloat16 g_qkv[(size_t)MROWS*3*CC];
__device__ __nv_bfloat16 g_o  [(size_t)MROWS*CC];
__device__ __nv_bfloat16 g_h1 [(size_t)MROWS*HID];
__device__ __nv_bfloat16 g_wq [(size_t)CC*3*CC];
__device__ __nv_bfloat16 g_wp [(size_t)CC*CC];
__device__ __nv_bfloat16 g_w1 [(size_t)CC*HID];
__device__ __nv_bfloat16 g_w2 [(size_t)HID*CC];
__device__ float         g_bm [(size_t)64*NHD*64*64];

__device__ __forceinline__ int remap_row(int m) {
    int w = m / NWIN, n = m - w * NWIN;
    int b = w >> 6, widx = w & 63;
    int wi = widx >> 3, wj = widx & 7;
    int ti = n / WSZ, tj = n - ti * WSZ;
    int i0 = wi * WSZ + ti + SSH; if (i0 >= HH) i0 -= HH;
    int j0 = wj * WSZ + tj + SSH; if (j0 >= HH) j0 -= HH;
    return b * LL + i0 * HH + j0;
}

// ---------------- all weights f32 -> bf16 in one kernel ----------------
#define CVT_N0 (CC*3*CC)
#define CVT_N1 (CVT_N0 + CC*CC)
#define CVT_N2 (CVT_N1 + CC*HID)
#define CVT_N3 (CVT_N2 + HID*CC)
__global__ void cvt_all(const float* __restrict__ s0, __nv_bfloat16* __restrict__ d0,
                        const float* __restrict__ s1, __nv_bfloat16* __restrict__ d1,
                        const float* __restrict__ s2, __nv_bfloat16* __restrict__ d2,
                        const float* __restrict__ s3, __nv_bfloat16* __restrict__ d3) {
    int i = blockIdx.x * 256 + threadIdx.x;
    if (i < CVT_N0)      d0[i]          = __float2bfloat16(s0[i]);
    else if (i < CVT_N1) d1[i - CVT_N0] = __float2bfloat16(s1[i - CVT_N0]);
    else if (i < CVT_N2) d2[i - CVT_N1] = __float2bfloat16(s2[i - CVT_N1]);
    else if (i < CVT_N3) d3[i - CVT_N2] = __float2bfloat16(s3[i - CVT_N2]);
}

// ---------------- precompute combined bias+mask tables -------------------
__global__ void bm_kernel(const float* __restrict__ rel_table,
                          const int* __restrict__ rel_index,
                          const float* __restrict__ mask,
                          float* __restrict__ bm) {
    int widx = blockIdx.x / NHD;
    int h    = blockIdx.x % NHD;
    float* dst = bm + (size_t)blockIdx.x * 4096;
    for (int e = threadIdx.x; e < 4096; e += 256) {
        int i = e >> 6, j = e & 63;
        float v = -1e30f;
        if (i < NWIN && j < NWIN)
            v = rel_table[rel_index[i * NWIN + j] * NHD + h]
              + mask[(size_t)widx * (NWIN * NWIN) + i * NWIN + j];
        dst[e] = v;
    }
}

// ---------------- LayerNorm (LN1): 8 rows/block, warp-per-row ------------
__global__ __launch_bounds__(256) void ln1_kernel(
    const float* __restrict__ x, const float* __restrict__ g,
    const float* __restrict__ b, __nv_bfloat16* __restrict__ y) {
    int warp = threadIdx.x >> 5, lane = threadIdx.x & 31;
    int m = blockIdx.x * 8 + warp;
    int r = remap_row(m);
    const float* xr = x + (size_t)r * CC;
    float v[6];
    float s = 0.f, s2 = 0.f;
    #pragma unroll
    for (int k = 0; k < 6; k++) {
        v[k] = xr[lane + 32 * k];
        s += v[k]; s2 += v[k] * v[k];
    }
    #pragma unroll
    for (int off = 16; off; off >>= 1) {
        s  += __shfl_xor_sync(~0u, s,  off);
        s2 += __shfl_xor_sync(~0u, s2, off);
    }
    float mean = s * (1.f / CC);
    float var  = s2 * (1.f / CC) - mean * mean;
    float inv  = rsqrtf(var + 1e-5f);
    __nv_bfloat16* yr = y + (size_t)m * CC;
    #pragma unroll
    for (int k = 0; k < 6; k++) {
        int c = lane + 32 * k;
        yr[c] = __float2bfloat16((v[k] - mean) * inv * g[c] + b[c]);
    }
}

// ---------------- shared mma/ldsm helpers ----------------
__device__ __forceinline__ void ldsm_x4(uint32_t& r0, uint32_t& r1, uint32_t& r2,
                                        uint32_t& r3, uint32_t a) {
    asm volatile("ldmatrix.sync.aligned.m8n8.x4.shared.b16 {%0,%1,%2,%3}, [%4];"
                 : "=r"(r0), "=r"(r1), "=r"(r2), "=r"(r3) : "r"(a));
}
__device__ __forceinline__ void ldsm_x4t(uint32_t& r0, uint32_t& r1, uint32_t& r2,
                                         uint32_t& r3, uint32_t a) {
    asm volatile("ldmatrix.sync.aligned.m8n8.x4.trans.shared.b16 {%0,%1,%2,%3}, [%4];"
                 : "=r"(r0), "=r"(r1), "=r"(r2), "=r"(r3) : "r"(a));
}
__device__ __forceinline__ void mma_bf16(float* d, uint32_t a0, uint32_t a1,
                                         uint32_t a2, uint32_t a3,
                                         uint32_t b0, uint32_t b1) {
    asm volatile(
        "mma.sync.aligned.m16n8k16.row.col.f32.bf16.bf16.f32 "
        "{%0,%1,%2,%3}, {%4,%5,%6,%7}, {%8,%9}, {%0,%1,%2,%3};"
        : "+f"(d[0]), "+f"(d[1]), "+f"(d[2]), "+f"(d[3])
        : "r"(a0), "r"(a1), "r"(a2), "r"(a3), "r"(b0), "r"(b1));
}
__device__ __forceinline__ void cp16(uint32_t saddr, const void* g) {
    asm volatile("cp.async.cg.shared.global [%0], [%1], 16;" :: "r"(saddr), "l"(g));
}
#define CP_COMMIT() asm volatile("cp.async.commit_group;")
#define CP_WAIT1()  asm volatile("cp.async.wait_group 1;")

// ---------------- bf16 GEMM: 128x64 tile, 3 stages, 4 CTAs/SM ------------
#define GBM 128
#define GBN 64
#define AST 40
#define BST 72
#define STG_ELTS (GBM*AST + 32*BST)
#define NSTG 3
#define GEMM_SMEM (NSTG * STG_ELTS * 2)   // 44544 B

template<int EPI, int KK, typename TOut>
__global__ __launch_bounds__(256, 4) void gemm_tc(
    const __nv_bfloat16* __restrict__ A, const __nv_bfloat16* __restrict__ B,
    const float* __restrict__ bias, TOut* __restrict__ C,
    int M, int N, const float* __restrict__ resid)
{
    extern __shared__ __align__(16) __nv_bfloat16 sm[];
    uint32_t sbase = (uint32_t)__cvta_generic_to_shared(sm);

    int bm = blockIdx.y * GBM, bn = blockIdx.x * GBN;
    int tid = threadIdx.x, lane = tid & 31;
    int lp = lane >> 2, lq = lane & 3;
    int warp = tid >> 5, wm = warp & 3, wn = warp >> 2;

    int a_r0 = tid >> 2;
    int a_c  = (tid & 3) * 8;
    int b_r  = tid >> 3;
    int b_c  = (tid & 7) * 8;
    int lrow = (lane & 7) + ((lane >> 3) & 1) * 8;
    int lcol = (lane >> 4) * 8;

    constexpr int nk = KK >> 5;
    constexpr int UNR = 6;
    float acc[2][4][4] = {};

    auto issue = [&](int it) {
        int s = it % NSTG;
        uint32_t sa = sbase + (uint32_t)(s * STG_ELTS) * 2;
        int k0 = it << 5;
        cp16(sa + (uint32_t)(a_r0 * AST + a_c) * 2,
             A + (size_t)(bm + a_r0) * KK + k0 + a_c);
        cp16(sa + (uint32_t)((a_r0 + 64) * AST + a_c) * 2,
             A + (size_t)(bm + a_r0 + 64) * KK + k0 + a_c);
        cp16(sa + (uint32_t)(GBM * AST + b_r * BST + b_c) * 2,
             B + (size_t)(k0 + b_r) * N + bn + b_c);
    };

    uint32_t af[2][2][4];
    uint32_t bf[2][2][4];

    auto ldfrags = [&](uint32_t sa, uint32_t sb, int ks, int buf) {
        #pragma unroll
        for (int mt = 0; mt < 2; mt++)
            ldsm_x4(af[buf][mt][0], af[buf][mt][1], af[buf][mt][2], af[buf][mt][3],
                    sa + (uint32_t)((wm * 32 + mt * 16 + lrow) * AST + ks * 16 + lcol) * 2);
        #pragma unroll
        for (int g = 0; g < 2; g++)
            ldsm_x4t(bf[buf][g][0], bf[buf][g][1], bf[buf][g][2], bf[buf][g][3],
                     sb + (uint32_t)((ks * 16 + lrow) * BST + wn * 32 + g * 16 + lcol) * 2);
    };
    auto mmas = [&](int buf) {
        #pragma unroll
        for (int mt = 0; mt < 2; mt++)
            #pragma unroll
            for (int nt = 0; nt < 4; nt++) {
                int g = nt >> 1, h = nt & 1;
                mma_bf16(acc[mt][nt],
                         af[buf][mt][0], af[buf][mt][1], af[buf][mt][2], af[buf][mt][3],
                         bf[buf][g][h * 2], bf[buf][g][h * 2 + 1]);
            }
    };

    issue(0); CP_COMMIT();
    issue(1); CP_COMMIT();
    #pragma unroll 1
    for (int it0 = 0; it0 < nk; it0 += UNR) {
        #pragma unroll
        for (int u = 0; u < UNR; u++) {
            int it = it0 + u;
            CP_WAIT1();
            __syncthreads();
            if (it + 2 < nk) issue(it + 2);
            CP_COMMIT();
            int s = it % NSTG;
            uint32_t sa = sbase + (uint32_t)(s * STG_ELTS) * 2;
            uint32_t sb = sa + GBM * AST * 2;
            ldfrags(sa, sb, 0, 0);
            ldfrags(sa, sb, 1, 1);
            mmas(0);
            mmas(1);
        }
    }

    int m0 = wm * 32, n0 = wn * 32;
    #pragma unroll
    for (int mt = 0; mt < 2; mt++) {
        #pragma unroll
        for (int half = 0; half < 2; half++) {
            int m = bm + m0 + mt * 16 + lp + half * 8;
            int row = m;
            #pragma unroll
            for (int nt = 0; nt < 4; nt++) {
                int n = bn + n0 + nt * 8 + 2 * lq;
                float v0 = acc[mt][nt][half * 2 + 0] + bias[n];
                float v1 = acc[mt][nt][half * 2 + 1] + bias[n + 1];
                if constexpr (EPI == 0) {
                    if (n < CC) { v0 *= QSCALE; v1 *= QSCALE; }
                    *(__nv_bfloat162*)&((__nv_bfloat16*)C)[(size_t)row * N + n] =
                        __floats2bfloat162_rn(v0, v1);
                } else if constexpr (EPI == 2) {
                    v0 = 0.5f * v0 * (1.f + erff(v0 * 0.70710678118654752f));
                    v1 = 0.5f * v1 * (1.f + erff(v1 * 0.70710678118654752f));
                    *(__nv_bfloat162*)&((__nv_bfloat16*)C)[(size_t)row * N + n] =
                        __floats2bfloat162_rn(v0, v1);
                } else {
                    const float2 cv = *(const float2*)&((float*)C)[(size_t)row * N + n];
                    *(float2*)&((float*)C)[(size_t)row * N + n] =
                        make_float2(v0 + cv.x, v1 + cv.y);
                }
            }
        }
    }
}

// ---------------- proj GEMM fused with residual + LN2 (64-row blocks) ----
// block 64x192, 256 threads, 8 warps (2M x 4N), warp 32x48.
#define PAST 40
#define PBST 200
#define PSTG_ELTS (64*PAST + 32*PBST)    // 2560+6400 = 8960
#define PNSTG 3
#define PRED_OFF (PNSTG*PSTG_ELTS)       // bf16 elts before red buffer
#define PROJ_SMEM (PNSTG*PSTG_ELTS*2 + 2*4*64*4)   // 53760 + 2048 = 55808 B

__global__ __launch_bounds__(256, 3) void proj_ln_tc(
    const __nv_bfloat16* __restrict__ A, const __nv_bfloat16* __restrict__ B,
    const float* __restrict__ bias, const float* __restrict__ x,
    float* __restrict__ out, const float* __restrict__ g2,
    const float* __restrict__ b2, __nv_bfloat16* __restrict__ xw)
{
    extern __shared__ __align__(16) __nv_bfloat16 sm[];
    uint32_t sbase = (uint32_t)__cvta_generic_to_shared(sm);
    float* redS = (float*)(sm + PRED_OFF);         // [4 wn][64 rows]
    float* redQ = redS + 4 * 64;

    int bm = blockIdx.x * 64;
    int tid = threadIdx.x, lane = tid & 31;
    int lp = lane >> 2, lq = lane & 3;
    int warp = tid >> 5, wm = warp & 1, wn = warp >> 1;
    int lrow = (lane & 7) + ((lane >> 3) & 1) * 8;
    int lcol = (lane >> 4) * 8;

    int a_r = tid >> 2;            // 0..63
    int a_c = (tid & 3) * 8;

    float acc[2][6][4] = {};

    auto issue = [&](int it) {
        int s = it % PNSTG;
        uint32_t sa = sbase + (uint32_t)(s * PSTG_ELTS) * 2;
        int k0 = it << 5;
        cp16(sa + (uint32_t)(a_r * PAST + a_c) * 2,
             A + (size_t)(bm + a_r) * CC + k0 + a_c);
        uint32_t sb = sa + 64 * PAST * 2;
        #pragma unroll
        for (int j = 0; j < 3; j++) {
            int u = tid + j * 256;
            int r = u / 24, c = (u - r * 24) * 8;
            cp16(sb + (uint32_t)(r * PBST + c) * 2, B + (size_t)(k0 + r) * CC + c);
        }
    };

    issue(0); CP_COMMIT();
    issue(1); CP_COMMIT();
    #pragma unroll
    for (int it = 0; it < 6; it++) {
        CP_WAIT1();
        __syncthreads();
        if (it + 2 < 6) issue(it + 2);
        CP_COMMIT();
        int s = it % PNSTG;
        uint32_t sa = sbase + (uint32_t)(s * PSTG_ELTS) * 2;
        uint32_t sb = sa + 64 * PAST * 2;
        #pragma unroll
        for (int ks = 0; ks < 2; ks++) {
            uint32_t a0, a1, a2, a3;
            ldsm_x4(a0, a1, a2, a3,
                    sa + (uint32_t)((wm * 32 + lrow) * PAST + ks * 16 + lcol) * 2);
            uint32_t a4, a5, a6, a7;
            ldsm_x4(a4, a5, a6, a7,
                    sa + (uint32_t)((wm * 32 + 16 + lrow) * PAST + ks * 16 + lcol) * 2);
            uint32_t bfr[3][4];
            #pragma unroll
            for (int g = 0; g < 3; g++)
                ldsm_x4t(bfr[g][0], bfr[g][1], bfr[g][2], bfr[g][3],
                         sb + (uint32_t)((ks * 16 + lrow) * PBST + wn * 48 + g * 16 + lcol) * 2);
            #pragma unroll
            for (int nt = 0; nt < 6; nt++) {
                int g = nt >> 1, h = nt & 1;
                mma_bf16(acc[0][nt], a0, a1, a2, a3, bfr[g][h * 2], bfr[g][h * 2 + 1]);
                mma_bf16(acc[1][nt], a4, a5, a6, a7, bfr[g][h * 2], bfr[g][h * 2 + 1]);
            }
        }
    }
    __syncthreads();

    int rowg[2][2];
    #pragma unroll
    for (int mt = 0; mt < 2; mt++)
        #pragma unroll
        for (int half = 0; half < 2; half++)
            rowg[mt][half] = remap_row(bm + wm * 32 + mt * 16 + lp + half * 8);

    float s_[2][2] = {}, q_[2][2] = {};
    #pragma unroll
    for (int mt = 0; mt < 2; mt++) {
        #pragma unroll
        for (int half = 0; half < 2; half++) {
            int row = rowg[mt][half];
            #pragma unroll
            for (int nt = 0; nt < 6; nt++) {
                int n = wn * 48 + nt * 8 + 2 * lq;
                float2 rv = *(const float2*)&x[(size_t)row * CC + n];
                float v0 = acc[mt][nt][half * 2 + 0] + bias[n]     + rv.x;
                float v1 = acc[mt][nt][half * 2 + 1] + bias[n + 1] + rv.y;
                acc[mt][nt][half * 2 + 0] = v0;
                acc[mt][nt][half * 2 + 1] = v1;
                s_[mt][half] += v0 + v1;
                q_[mt][half] += v0 * v0 + v1 * v1;
            }
        }
    }
    #pragma unroll
    for (int mt = 0; mt < 2; mt++)
        #pragma unroll
        for (int half = 0; half < 2; half++) {
            s_[mt][half] += __shfl_xor_sync(~0u, s_[mt][half], 1);
            s_[mt][half] += __shfl_xor_sync(~0u, s_[mt][half], 2);
            q_[mt][half] += __shfl_xor_sync(~0u, q_[mt][half], 1);
            q_[mt][half] += __shfl_xor_sync(~0u, q_[mt][half], 2);
        }
    if (lq == 0) {
        #pragma unroll
        for (int mt = 0; mt < 2; mt++)
            #pragma unroll
            for (int half = 0; half < 2; half++) {
                int lr = wm * 32 + mt * 16 + lp + half * 8;
                redS[wn * 64 + lr] = s_[mt][half];
                redQ[wn * 64 + lr] = q_[mt][half];
            }
    }
    __syncthreads();

    #pragma unroll
    for (int mt = 0; mt < 2; mt++) {
        #pragma unroll
        for (int half = 0; half < 2; half++) {
            int lr  = wm * 32 + mt * 16 + lp + half * 8;
            int row = rowg[mt][half];
            float ts = redS[lr] + redS[64 + lr] + redS[128 + lr] + redS[192 + lr];
            float tq = redQ[lr] + redQ[64 + lr] + redQ[128 + lr] + redQ[192 + lr];
            float mean = ts * (1.f / CC);
            float var  = tq * (1.f / CC) - mean * mean;
            float inv  = rsqrtf(var + 1e-5f);
            #pragma unroll
            for (int nt = 0; nt < 6; nt++) {
                int n = wn * 48 + nt * 8 + 2 * lq;
                float v0 = acc[mt][nt][half * 2 + 0];
                float v1 = acc[mt][nt][half * 2 + 1];
                *(float2*)&out[(size_t)row * CC + n] = make_float2(v0, v1);
                float y0 = (v0 - mean) * inv * g2[n]     + b2[n];
                float y1 = (v1 - mean) * inv * g2[n + 1] + b2[n + 1];
                *(__nv_bfloat162*)&xw[(size_t)row * CC + n] =
                    __floats2bfloat162_rn(y0, y1);
            }
        }
    }
}

// ---------------- tensor-core windowed attention ----------------
#define NP  64
#define QST 40
#define PST 72

__global__ __launch_bounds__(128) void attn_tc(
    const __nv_bfloat16* __restrict__ qkv, const float* __restrict__ bm_tab,
    __nv_bfloat16* __restrict__ o)
{
    __shared__ __align__(16) __nv_bfloat16 sQ[NP * QST];
    __shared__ __align__(16) __nv_bfloat16 sK[NP * QST];
    __shared__ __align__(16) __nv_bfloat16 sV[NP * QST];
    __shared__ __align__(16) __nv_bfloat16 sP[NP * PST];

    int w = blockIdx.x, h = blockIdx.y, widx = w & 63;
    int tid = threadIdx.x, lane = tid & 31, warp = tid >> 5;
    int lp = lane >> 2, lq = lane & 3;
    int lrow = (lane & 7) + ((lane >> 3) & 1) * 8;
    int lcol = (lane >> 4) * 8;

    const float* bm = bm_tab + (size_t)(widx * NHD + h) * 4096;

    const __nv_bfloat16* qbase = qkv + (size_t)(w * NWIN) * (3 * CC) + h * HD;
    for (int idx = tid; idx < 3 * 64 * 4; idx += 128) {
        int t   = idx >> 8;
        int row = (idx >> 2) & 63;
        int ch  = idx & 3;
        uint4 val = make_uint4(0, 0, 0, 0);
        if (row < NWIN)
            val = *(const uint4*)(qbase + (size_t)row * (3 * CC) + t * CC + ch * 8);
        __nv_bfloat16* dst = (t == 0) ? sQ : (t == 1) ? sK : sV;
        *(uint4*)(dst + row * QST + ch * 8) = val;
    }
    __syncthreads();

    uint32_t qb = (uint32_t)__cvta_generic_to_shared(sQ);
    uint32_t kb = (uint32_t)__cvta_generic_to_shared(sK);
    uint32_t vb = (uint32_t)__cvta_generic_to_shared(sV);
    uint32_t pb = (uint32_t)__cvta_generic_to_shared(sP);

    float S[8][4] = {};
    #pragma unroll
    for (int ks = 0; ks < 2; ks++) {
        uint32_t a0, a1, a2, a3;
        ldsm_x4(a0, a1, a2, a3,
                qb + (uint32_t)((warp * 16 + lrow) * QST + ks * 16 + lcol) * 2);
        #pragma unroll
        for (int g = 0; g < 4; g++) {
            uint32_t r0, r1, r2, r3;
            ldsm_x4(r0, r1, r2, r3,
                    kb + (uint32_t)((g * 16 + lrow) * QST + ks * 16 + lcol) * 2);
            mma_bf16(S[g * 2],     a0, a1, a2, a3, r0, r2);
            mma_bf16(S[g * 2 + 1], a0, a1, a2, a3, r1, r3);
        }
    }

    int i0 = warp * 16 + lp;
    float mx0 = -1e30f, mx1 = -1e30f;
    #pragma unroll
    for (int nt = 0; nt < 8; nt++) {
        int c = nt * 8 + 2 * lq;
        float2 b0 = *(const float2*)&bm[i0 * 64 + c];
        float2 b1 = *(const float2*)&bm[(i0 + 8) * 64 + c];
        S[nt][0] += b0.x; S[nt][1] += b0.y;
        S[nt][2] += b1.x; S[nt][3] += b1.y;
        mx0 = fmaxf(mx0, fmaxf(S[nt][0], S[nt][1]));
        mx1 = fmaxf(mx1, fmaxf(S[nt][2], S[nt][3]));
    }
    mx0 = fmaxf(mx0, __shfl_xor_sync(~0u, mx0, 1));
    mx0 = fmaxf(mx0, __shfl_xor_sync(~0u, mx0, 2));
    mx1 = fmaxf(mx1, __shfl_xor_sync(~0u, mx1, 1));
    mx1 = fmaxf(mx1, __shfl_xor_sync(~0u, mx1, 2));
    float sm0 = 0.f, sm1 = 0.f;
    #pragma unroll
    for (int nt = 0; nt < 8; nt++) {
        S[nt][0] = __expf(S[nt][0] - mx0);
        S[nt][1] = __expf(S[nt][1] - mx0);
        S[nt][2] = __expf(S[nt][2] - mx1);
        S[nt][3] = __expf(S[nt][3] - mx1);
        sm0 += S[nt][0] + S[nt][1];
        sm1 += S[nt][2] + S[nt][3];
    }
    sm0 += __shfl_xor_sync(~0u, sm0, 1);
    sm0 += __shfl_xor_sync(~0u, sm0, 2);
    sm1 += __shfl_xor_sync(~0u, sm1, 1);
    sm1 += __shfl_xor_sync(~0u, sm1, 2);
    float inv0 = 1.f / sm0, inv1 = 1.f / sm1;
    #pragma unroll
    for (int nt = 0; nt < 8; nt++) {
        int c = nt * 8 + 2 * lq;
        *(__nv_bfloat162*)(sP + i0 * PST + c) =
            __floats2bfloat162_rn(S[nt][0] * inv0, S[nt][1] * inv0);
        *(__nv_bfloat162*)(sP + (i0 + 8) * PST + c) =
            __floats2bfloat162_rn(S[nt][2] * inv1, S[nt][3] * inv1);
    }
    __syncwarp();

    float O[4][4] = {};
    #pragma unroll
    for (int kst = 0; kst < 4; kst++) {
        uint32_t a0, a1, a2, a3;
        ldsm_x4(a0, a1, a2, a3,
                pb + (uint32_t)((warp * 16 + lrow) * PST + kst * 16 + lcol) * 2);
        #pragma unroll
        for (int g = 0; g < 2; g++) {
            uint32_t r0, r1, r2, r3;
            ldsm_x4t(r0, r1, r2, r3,
                     vb + (uint32_t)((kst * 16 + lrow) * QST + g * 16 + lcol) * 2);
            mma_bf16(O[g * 2],     a0, a1, a2, a3, r0, r1);
            mma_bf16(O[g * 2 + 1], a0, a1, a2, a3, r2, r3);
        }
    }

    __nv_bfloat16* obase = o + (size_t)(w * NWIN) * CC + h * HD;
    #pragma unroll
    for (int half = 0; half < 2; half++) {
        int i = i0 + half * 8;
        if (i < NWIN) {
            #pragma unroll
            for (int nt = 0; nt < 4; nt++) {
                int d = nt * 8 + 2 * lq;
                *(__nv_bfloat162*)(obase + (size_t)i * CC + d) =
                    __floats2bfloat162_rn(O[nt][half * 2], O[nt][half * 2 + 1]);
            }
        }
    }
}

// ---------------- launch ----------------
extern "C" void kernel_launch(void* const* d_in, const int* in_sizes, int n_in,
                              void* d_out, int out_size) {
    const float* x        = (const float*)d_in[0];
    const float* norm1_g  = (const float*)d_in[1];
    const float* norm1_b  = (const float*)d_in[2];
    const float* qkv_w    = (const float*)d_in[3];
    const float* qkv_b    = (const float*)d_in[4];
    const float* proj_w   = (const float*)d_in[5];
    const float* proj_b   = (const float*)d_in[6];
    const float* norm2_g  = (const float*)d_in[7];
    const float* norm2_b  = (const float*)d_in[8];
    const float* fc1_w    = (const float*)d_in[9];
    const float* fc1_b    = (const float*)d_in[10];
    const float* fc2_w    = (const float*)d_in[11];
    const float* fc2_b    = (const float*)d_in[12];
    const float* rel_table= (const float*)d_in[13];
    const int*   rel_index= (const int*)  d_in[14];
    const float* mask     = (const float*)d_in[15];
    float* out = (float*)d_out;

    __nv_bfloat16 *xw, *qkv, *o, *h1, *wq, *wp, *w1, *w2;
    float* bm;
    cudaGetSymbolAddress((void**)&xw,  g_xw);
    cudaGetSymbolAddress((void**)&qkv, g_qkv);
    cudaGetSymbolAddress((void**)&o,   g_o);
    cudaGetSymbolAddress((void**)&h1,  g_h1);
    cudaGetSymbolAddress((void**)&wq,  g_wq);
    cudaGetSymbolAddress((void**)&wp,  g_wp);
    cudaGetSymbolAddress((void**)&w1,  g_w1);
    cudaGetSymbolAddress((void**)&w2,  g_w2);
    cudaGetSymbolAddress((void**)&bm,  g_bm);

    cudaFuncSetAttribute((const void*)gemm_tc<0, CC, __nv_bfloat16>,
                         cudaFuncAttributeMaxDynamicSharedMemorySize, GEMM_SMEM);
    cudaFuncSetAttribute((const void*)gemm_tc<2, CC, __nv_bfloat16>,
                         cudaFuncAttributeMaxDynamicSharedMemorySize, GEMM_SMEM);
    cudaFuncSetAttribute((const void*)gemm_tc<3, HID, float>,
                         cudaFuncAttributeMaxDynamicSharedMemorySize, GEMM_SMEM);
    cudaFuncSetAttribute((const void*)proj_ln_tc,
                         cudaFuncAttributeMaxDynamicSharedMemorySize, PROJ_SMEM);

    cvt_all<<<(CVT_N3 + 255) / 256, 256>>>(qkv_w, wq, proj_w, wp, fc1_w, w1, fc2_w, w2);
    bm_kernel<<<64 * NHD, 256>>>(rel_table, rel_index, mask, bm);

    ln1_kernel<<<MROWS / 8, 256>>>(x, norm1_g, norm1_b, xw);
    gemm_tc<0, CC, __nv_bfloat16><<<dim3((3*CC)/GBN, MROWS/GBM), 256, GEMM_SMEM>>>(
        xw, wq, qkv_b, qkv, MROWS, 3*CC, nullptr);
    attn_tc<<<dim3(BW, NHD), 128>>>(qkv, bm, o);
    proj_ln_tc<<<MROWS/64, 256, PROJ_SMEM>>>(o, wp, proj_b, x, out,
                                             norm2_g, norm2_b, xw);
    gemm_tc<2, CC, __nv_bfloat16><<<dim3(HID/GBN, MROWS/GBM), 256, GEMM_SMEM>>>(
        xw, w1, fc1_b, h1, MROWS, HID, nullptr);
    gemm_tc<3, HID, float><<<dim3(CC/GBN, MROWS/GBM), 256, GEMM_SMEM>>>(
        h1, w2, fc2_b, out, MROWS, CC, nullptr);
}